// round 17
// baseline (speedup 1.0000x reference)
#include <cuda_runtime.h>
#include <cuda_fp16.h>
#include <math.h>
#include <stdint.h>

// ---------------------------------------------------------------------------
// AIO_DownsampleCouplingBlock — Round 17: A-RESIDENT smem. The full A tile
// (with conv halo) is loaded into smem ONCE per CTA; all iterations read it
// via lane-addressed ldmatrix with tap offsets. Only B streams per iteration
// (2-stage ping-pong). Fused affine epilogues (validated r11/r16 layout).
// ---------------------------------------------------------------------------

__device__ __align__(16) __half g_xh[32 * 4 * 32 * 32 * 48];  // x1 phases [b][ph][h'][w'][48]
__device__ __align__(16) __half g_y2h[32 * 32 * 32 * 192];    // y2 NHWC half
__device__ __align__(16) __half g_wp1[9 * 384 * 48];          // conv1 w [tap][nn][48]
__device__ __align__(16) __half g_wp2[27 * 384 * 64];         // conv2 w [st][nn][64]
__device__ int   g_invperm[384];
__device__ float g_scale[384];

__device__ __forceinline__ void cp_async16(unsigned dst, const void* src) {
    asm volatile("cp.async.cg.shared.global [%0], [%1], 16;\n"
                 :: "r"(dst), "l"(src));
}
__device__ __forceinline__ void cp_async16z(unsigned dst, const void* src, int sz) {
    asm volatile("cp.async.cg.shared.global [%0], [%1], 16, %2;\n"
                 :: "r"(dst), "l"(src), "r"(sz));
}
__device__ __forceinline__ void ldsm4(uint32_t& r0, uint32_t& r1,
                                      uint32_t& r2, uint32_t& r3, unsigned addr) {
    asm volatile("ldmatrix.sync.aligned.m8n8.x4.shared.b16 {%0,%1,%2,%3}, [%4];"
                 : "=r"(r0), "=r"(r1), "=r"(r2), "=r"(r3) : "r"(addr));
}

// ---------------------------------------------------------------------------
__global__ void prep_kernel(const float* __restrict__ perm_w,
                            const float* __restrict__ act_norm) {
    int p = threadIdx.x;
    if (p < 384) {
        int o_found = 0;
        for (int o = 0; o < 384; ++o)
            if (perm_w[o * 384 + p] > 0.5f) o_found = o;
        g_invperm[p] = o_found;
        g_scale[p] = 0.2f * log1pf(expf(0.5f * act_norm[p]));
    }
}

// nn remap (128-col N-blocks): block y = nn>>7, r = nn&127:
//   r < 64 : n = y*64 + r ; r >= 64 : n = 192 + y*64 + (r-64)
__device__ __forceinline__ int nn_to_n(int nn) {
    int yb = nn >> 7, r = nn & 127;
    return (r < 64) ? (yb * 64 + r) : (192 + yb * 64 + (r - 64));
}

// both weight packs: dst[st][nn(384)][k(KB)], exact K (no pad)
__global__ void pack_all_kernel(const float* __restrict__ w_hi,
                                const float* __restrict__ w_lo) {
    const int T1 = 9 * 384 * 48;
    const int T2 = 27 * 384 * 64;
    int idx = blockIdx.x * 256 + threadIdx.x;
    if (idx < T1) {
        int k = idx % 48;
        int nn = (idx / 48) % 384;
        int tap = idx / (48 * 384);
        int n = nn_to_n(nn);
        g_wp1[idx] = __float2half(w_hi[(n * 48 + k) * 9 + tap]);
    } else if (idx < T1 + T2) {
        int j = idx - T1;
        int k = j % 64;
        int nn = (j / 64) % 384;
        int st = j / (64 * 384);          // tap = st/3, cblk = st%3
        int n = nn_to_n(nn);
        int tap = st / 3;
        int c = (st % 3) * 64 + k;
        g_wp2[j] = __float2half(w_lo[(n * 192 + c) * 9 + tap]);
    }
}

// x (NCHW f32, first 48 ch) -> g_xh phase-split [b][ph][h'][w'][48] half.
__global__ __launch_bounds__(256) void x2h_kernel(const float* __restrict__ x) {
    __shared__ float tile[48][65];
    const int b = blockIdx.x >> 6, ih = blockIdx.x & 63;
    for (int idx = threadIdx.x; idx < 48 * 64; idx += 256) {
        const int c = idx >> 6, w = idx & 63;
        tile[c][w] = x[(((size_t)b * 96 + c) * 64 + ih) * 64 + w];
    }
    __syncthreads();
    const int ph_h = (ih & 1) << 1, hp = ih >> 1;
    for (int idx = threadIdx.x; idx < 64 * 24; idx += 256) {
        const int iw = idx / 24, cp = idx % 24;
        const int ph = ph_h | (iw & 1), wp = iw >> 1;
        __half2 v = __floats2half2_rn(tile[2 * cp][iw], tile[2 * cp + 1][iw]);
        *(__half2*)&g_xh[((((size_t)(b * 4 + ph)) * 32 + hp) * 32 + wp) * 48 + 2 * cp] = v;
    }
}

// ---------------------------------------------------------------------------
// fused conv + affine epilogue, A-resident smem.
// 256 thr / 8 warps, 2 CTAs/SM. Warp grid 2(M) x 4(N), warp tile 64x32.
// BM=128, BN=128 (64 lo + 64 paired hi).
// WHICH=1 (conv1): A = 4 phases x 5 rows x 32 w x 48ch, pix stride 112B.
// WHICH=2 (conv2): A = 6 rows x 32 w x 192ch, pix stride 400B.
// B: 2-stage ping-pong [nn(128)][KB], row stride KB*2+16.
// ---------------------------------------------------------------------------
template <int KB, int CH, int CTOT, int WHICH>
__global__ __launch_bounds__(256, 2) void conv_fused(
    const float* __restrict__ x,
    const float* __restrict__ bias,
    const float* __restrict__ act_offset,
    float* __restrict__ outp) {
    extern __shared__ __align__(16) char smem[];

    constexpr int PSTR   = CTOT * 2 + 16;          // bytes per resident pixel
    constexpr int NPIX   = (WHICH == 1) ? 640 : 192;
    constexpr int ZPIX   = NPIX;                   // zero-pixel index
    constexpr int ABYTES = (NPIX + 1) * PSTR;
    constexpr int BROWB  = KB * 2 + 16;
    constexpr int BSTG   = 128 * BROWB;
    constexpr int KSTEPS = KB / 16;
    constexpr int CHKH   = KB / 16;                // B chunks per (tid&1) half
    constexpr int NIT    = 9 * CH;

    const __half* inp = (WHICH == 1) ? (const __half*)g_xh : (const __half*)g_y2h;
    const __half* wp  = (WHICH == 1) ? (const __half*)g_wp1 : (const __half*)g_wp2;
    constexpr int XOFF  = (WHICH == 1) ? 48 : 0;
    constexpr int PBASE = (WHICH == 1) ? 192 : 0;

    const int tid  = threadIdx.x;
    const int lane = tid & 31;
    const int warp = tid >> 5;
    const int wm = warp >> 2;
    const int wn = warp & 3;
    const int g4 = lane >> 2;
    const int t4 = lane & 3;

    const int bm   = blockIdx.x;
    const int bimg = bm >> 3;
    const int h0   = (bm & 7) * 4;
    const int yb   = blockIdx.y;
    const int n0   = yb * 128;

    const unsigned smemBase = (unsigned)__cvta_generic_to_shared(smem);
    const unsigned aBase  = smemBase;
    const unsigned bBase0 = smemBase + (unsigned)ABYTES;
    const unsigned bBase1 = bBase0 + (unsigned)BSTG;

    const int aKoffL = (lane >> 4) << 4;
    const int bRow0 = wn * 16 + ((lane >> 4) << 3) + (lane & 7);
    const int bKoffL = ((lane >> 3) & 1) << 4;

    // per-thread fragment row components (m = wm*64 + mi*16 + (lane&15))
    int rm5[4], rml[4];
#pragma unroll
    for (int mi = 0; mi < 4; ++mi) {
        const int m = wm * 64 + mi * 16 + (lane & 15);
        rm5[mi] = m >> 5;
        rml[mi] = m & 31;
    }

    float acc[4][4][4];
#pragma unroll
    for (int i = 0; i < 4; i++)
#pragma unroll
        for (int j = 0; j < 4; j++)
#pragma unroll
            for (int k = 0; k < 4; k++) acc[i][j][k] = 0.f;

    // B stage loader (division-free): row = tid>>1, ch = (tid&1)*CHKH + p
    auto load_B = [&](int it, unsigned buf) {
        const __half* wsrc = wp + (size_t)it * (384 * KB) + (size_t)n0 * KB;
        const int row = tid >> 1;
        const int ch0 = (tid & 1) * CHKH;
        const unsigned dst = buf + (unsigned)(row * BROWB + ch0 * 16);
        const __half* src = wsrc + row * KB + ch0 * 8;
#pragma unroll
        for (int p = 0; p < CHKH; ++p)
            cp_async16(dst + p * 16u, src + p * 8);
    };

    // ---- prologue: resident A load + B0, one group ----
    if (WHICH == 1) {
        // 640 pixels x 6 chunks + 6 zero-row chunks = 3846 tasks
        for (int j = 0; j < 16; ++j) {
            const int idx = tid + 256 * j;
            if (idx < 3846) {
                const int pix = idx / 6, ch = idx - pix * 6;
                const unsigned dst = aBase + (unsigned)(pix * PSTR + ch * 16);
                if (pix < 640) {
                    const int ph = pix / 160, rem = pix - ph * 160;
                    const int lr = rem >> 5, wpx = rem & 31;
                    const int hp = h0 - 1 + lr;       // hp <= 31 guaranteed
                    const bool ok = (hp >= 0);
                    const __half* src = ok
                        ? inp + (((size_t)(bimg * 4 + ph) * 32 + hp) * 32 + wpx) * 48 + ch * 8
                        : inp;
                    cp_async16z(dst, src, ok ? 16 : 0);
                } else {
                    cp_async16z(dst, inp, 0);
                }
            }
        }
    } else {
        // 192 pixels x 24 chunks + 24 zero-row chunks = 4632 tasks
        for (int j = 0; j < 19; ++j) {
            const int idx = tid + 256 * j;
            if (idx < 4632) {
                const int pix = idx / 24, ch = idx - pix * 24;
                const unsigned dst = aBase + (unsigned)(pix * PSTR + ch * 16);
                if (pix < 192) {
                    const int ihl = pix >> 5, iw = pix & 31;
                    const int ih = h0 - 1 + ihl;
                    const bool ok = (ih >= 0) && (ih < 32);
                    const __half* src = ok
                        ? inp + (((size_t)(bimg * 32 + ih)) * 32 + iw) * 192 + ch * 8
                        : inp;
                    cp_async16z(dst, src, ok ? 16 : 0);
                } else {
                    cp_async16z(dst, inp, 0);
                }
            }
        }
    }
    load_B(0, bBase0);
    asm volatile("cp.async.commit_group;\n" ::: "memory");

    int itg = 0;
    int dh = -1, dw = -1;
#pragma unroll 1
    for (int tap = 0; tap < 9; ++tap) {
        // lane A base addresses for this tap (zero-row redirect at edges)
        unsigned aaddr[4];
        if (WHICH == 1) {
            const int ph   = ((dh & 1) << 1) | (dw & 1);
            const int hoff = dh >> 1;
            const int woff = dw >> 1;
#pragma unroll
            for (int mi = 0; mi < 4; ++mi) {
                const int iw = rml[mi] + woff;
                const int hp = h0 + rm5[mi] + hoff;
                const bool ok = (hp >= 0) && (iw >= 0);
                const int lr = rm5[mi] + hoff + 1;
                const int pix = ok ? (ph * 160 + lr * 32 + iw) : ZPIX;
                aaddr[mi] = aBase + (unsigned)(pix * PSTR + aKoffL);
            }
        } else {
#pragma unroll
            for (int mi = 0; mi < 4; ++mi) {
                const int iw = rml[mi] + dw;
                const int ih = h0 + rm5[mi] + dh;
                const bool ok = (ih >= 0) && (ih < 32) && (iw >= 0) && (iw < 32);
                const int pix = ok ? ((rm5[mi] + dh + 1) * 32 + iw) : ZPIX;
                aaddr[mi] = aBase + (unsigned)(pix * PSTR + aKoffL);
            }
        }

#pragma unroll 1
        for (int cb = 0; cb < CH; ++cb) {
            asm volatile("cp.async.wait_group 0;\n" ::: "memory");
            __syncthreads();
            if (itg + 1 < NIT)
                load_B(itg + 1, ((itg + 1) & 1) ? bBase1 : bBase0);
            asm volatile("cp.async.commit_group;\n" ::: "memory");

            const unsigned bB = (itg & 1) ? bBase1 : bBase0;
            const int colbase = cb * (KB * 2);
#pragma unroll
            for (int step = 0; step < KSTEPS; ++step) {
                const int kb = colbase + step * 32;
                uint32_t af[4][4];
#pragma unroll
                for (int mi = 0; mi < 4; ++mi)
                    ldsm4(af[mi][0], af[mi][1], af[mi][2], af[mi][3],
                          aaddr[mi] + (unsigned)kb);
                uint32_t bf[4][2];
                const int kbb = step * 32;
                ldsm4(bf[0][0], bf[0][1], bf[1][0], bf[1][1],
                      bB + (unsigned)(bRow0 * BROWB + kbb + bKoffL));
                ldsm4(bf[2][0], bf[2][1], bf[3][0], bf[3][1],
                      bB + (unsigned)((bRow0 + 64) * BROWB + kbb + bKoffL));
#pragma unroll
                for (int mi = 0; mi < 4; ++mi)
#pragma unroll
                    for (int ni = 0; ni < 4; ++ni) {
                        asm volatile(
                            "mma.sync.aligned.m16n8k16.row.col.f32.f16.f16.f32 "
                            "{%0,%1,%2,%3}, {%4,%5,%6,%7}, {%8,%9}, {%0,%1,%2,%3};"
                            : "+f"(acc[mi][ni][0]), "+f"(acc[mi][ni][1]),
                              "+f"(acc[mi][ni][2]), "+f"(acc[mi][ni][3])
                            : "r"(af[mi][0]), "r"(af[mi][1]),
                              "r"(af[mi][2]), "r"(af[mi][3]),
                              "r"(bf[ni][0]), "r"(bf[ni][1]));
                    }
            }
            ++itg;
        }
        if (++dw > 1) { dw = -1; ++dh; }
    }

    // ---- fused affine epilogue (validated layout) ------------------------
#pragma unroll
    for (int ni = 0; ni < 2; ++ni) {
        const int c = yb * 64 + wn * 16 + ni * 8 + 2 * t4;   // even
        const float bl0 = bias[c],        bl1 = bias[c + 1];
        const float bh0 = bias[c + 192],  bh1 = bias[c + 193];
        const int p0 = PBASE + c, p1 = PBASE + c + 1;
        const float sc0 = g_scale[p0], sc1 = g_scale[p1];
        const float ao0 = act_offset[p0], ao1 = act_offset[p1];
        const int o0 = g_invperm[p0], o1 = g_invperm[p1];
        const int cc = c >> 2, ii = (c >> 1) & 1;
        const float* xrowb = x + (((size_t)bimg * 96 + XOFF + cc) * 64 + ii) * 64;
#pragma unroll
        for (int mi = 0; mi < 4; ++mi) {
#pragma unroll
            for (int rr = 0; rr < 2; ++rr) {
                const int m = wm * 64 + mi * 16 + g4 + rr * 8;
                const int h = h0 + (m >> 5);
                const int w = m & 31;
                const float lo0 = acc[mi][ni][rr * 2 + 0] + bl0;
                const float lo1 = acc[mi][ni][rr * 2 + 1] + bl1;
                const float hi0 = acc[mi][ni + 2][rr * 2 + 0] + bh0;
                const float hi1 = acc[mi][ni + 2][rr * 2 + 1] + bh1;
                const float2 xd = *(const float2*)&xrowb[(size_t)(2 * h) * 64 + 2 * w];
                const float y0 = xd.x * expf(2.0f * tanhf(0.2f * lo0)) + hi0;
                const float y1 = xd.y * expf(2.0f * tanhf(0.2f * lo1)) + hi1;
                const int hw = h * 32 + w;
                if (WHICH == 1) {
                    *(__half2*)&g_y2h[(((size_t)(bimg * 32 + h) * 32) + w) * 192 + c] =
                        __floats2half2_rn(y0, y1);
                }
                outp[(((size_t)(bimg * 384 + o0)) << 10) + hw] = y0 * sc0 + ao0;
                outp[(((size_t)(bimg * 384 + o1)) << 10) + hw] = y1 * sc1 + ao1;
            }
        }
    }
}

// ---------------------------------------------------------------------------
extern "C" void kernel_launch(void* const* d_in, const int* in_sizes, int n_in,
                              void* d_out, int out_size) {
    const float* x          = (const float*)d_in[0];
    const float* w_hi       = (const float*)d_in[1];
    const float* b_hi       = (const float*)d_in[2];
    const float* w_lo       = (const float*)d_in[3];
    const float* b_lo       = (const float*)d_in[4];
    const float* act_norm   = (const float*)d_in[5];
    const float* act_offset = (const float*)d_in[6];
    const float* perm_w     = (const float*)d_in[7];
    float* out = (float*)d_out;

    // conv1: A (641*112) + B 2*128*112 = 71,792 + 28,672 = 100,464 B (2 CTAs/SM)
    // conv2: A (193*400) + B 2*128*144 = 77,200 + 36,864 = 114,064 B (2 CTAs/SM)
    const int SMEM1 = 641 * 112 + 2 * 128 * 112;
    const int SMEM2 = 193 * 400 + 2 * 128 * 144;

    cudaFuncSetAttribute(conv_fused<48, 1, 48, 1>,
                         cudaFuncAttributeMaxDynamicSharedMemorySize, SMEM1);
    cudaFuncSetAttribute(conv_fused<64, 3, 192, 2>,
                         cudaFuncAttributeMaxDynamicSharedMemorySize, SMEM2);

    prep_kernel<<<1, 384>>>(perm_w, act_norm);
    {
        int total = 9 * 384 * 48 + 27 * 384 * 64;
        pack_all_kernel<<<(total + 255) / 256, 256>>>(w_hi, w_lo);
    }
    x2h_kernel<<<32 * 64, 256>>>(x);

    conv_fused<48, 1, 48, 1><<<dim3(256, 3), 256, SMEM1>>>(
        x, b_hi, act_offset, out);

    conv_fused<64, 3, 192, 2><<<dim3(256, 3), 256, SMEM2>>>(
        x, b_lo, act_offset, out);
}